// round 15
// baseline (speedup 1.0000x reference)
#include <cuda_runtime.h>
#include <cstdint>

// CapsuleLayer dynamic routing. C=10,B=128,N=1152,IN=8,OUT=16, 3 iters.
//   1) tiled transpose W -> Wt4[c][j][n]; simple transpose x -> xT4[b][j][n]
//   2) fused priors + routing, one CTA per (c, batch-pair), 576 threads.
// Phase A streams W via cp.async (LDGSTS) through a 2-slot smem ring:
// loads hold no registers in flight, each thread consumes only its OWN
// staged data (no barriers), LDS 29-cyc latency replaces LDG ~250-cyc.
// Priors stay register-resident, packed f32x2 (fma.rn.f32x2). Phase B =
// R14: shift-free softmax, fused logit-update sweeps, warp butterfly ->
// vred -> warp-0 squash; iteration 0 uses logits==0 -> uniform (S = N).

#define CCAP   10
#define BD     128
#define ND     1152
#define OUTD   16
#define HALF   576
#define THREADS 576
#define NWARPS  18
#define NBLOCKS (CCAP * BD / 2)   // 640

#define WT_ELEMS (CCAP * 32 * ND)   // 368,640 float4 (5.9 MB)
#define XT_ELEMS (BD * 2 * ND)      // 294,912 float4 (4.7 MB)

__device__ float4 g_Wt[WT_ELEMS];
__device__ float4 g_xT[XT_ELEMS];

typedef unsigned long long u64;

__device__ __forceinline__ u64 pk2(float a, float b) {
    u64 r; asm("mov.b64 %0, {%1, %2};" : "=l"(r) : "f"(a), "f"(b)); return r;
}
__device__ __forceinline__ void upk2(float& a, float& b, u64 v) {
    asm("mov.b64 {%0, %1}, %2;" : "=f"(a), "=f"(b) : "l"(v));
}
__device__ __forceinline__ u64 ffma2(u64 a, u64 b, u64 c) {
    u64 d; asm("fma.rn.f32x2 %0, %1, %2, %3;" : "=l"(d) : "l"(a), "l"(b), "l"(c)); return d;
}
__device__ __forceinline__ u64 fmul2(u64 a, u64 b) {
    u64 d; asm("mul.rn.f32x2 %0, %1, %2;" : "=l"(d) : "l"(a), "l"(b)); return d;
}
__device__ __forceinline__ u64 fadd2(u64 a, u64 b) {
    u64 d; asm("add.rn.f32x2 %0, %1, %2;" : "=l"(d) : "l"(a), "l"(b)); return d;
}
__device__ __forceinline__ void cp16(uint32_t d, const float4* s) {
    asm volatile("cp.async.cg.shared.global [%0], [%1], 16;"
                 :: "r"(d), "l"((size_t)__cvta_generic_to_global(s)));
}

// ---------------- Kernel 1: transposes ----------------
#define TP_WBLOCKS (CCAP * 36)          // 360
#define TP_XBLOCKS (XT_ELEMS / 1024)    // 288

__global__ void transpose_inputs_kernel(const float4* __restrict__ W4,
                                        const float4* __restrict__ X4)
{
    if (blockIdx.x < TP_WBLOCKS) {
        __shared__ float4 tile[32][33];
        const int c  = blockIdx.x / 36;
        const int n0 = (blockIdx.x % 36) * 32;
        #pragma unroll
        for (int k = 0; k < 4; k++) {
            int flat = threadIdx.x + k * 256;
            int jr = flat & 31, nr = flat >> 5;
            tile[jr][nr] = W4[((size_t)(c * ND + n0 + nr)) * 32 + jr];
        }
        __syncthreads();
        #pragma unroll
        for (int k = 0; k < 4; k++) {
            int flat = threadIdx.x + k * 256;
            int nr = flat & 31, jr = flat >> 5;
            g_Wt[(size_t)(c * 32 + jr) * ND + n0 + nr] = tile[jr][nr];
        }
    } else {
        int base = (blockIdx.x - TP_WBLOCKS) * 1024 + threadIdx.x;
        #pragma unroll
        for (int k = 0; k < 4; k++) {
            int e = base + k * 256;
            int n = e % ND;
            int t = e / ND;
            int j = t & 1;
            int b = t >> 1;
            g_xT[e] = X4[((size_t)b * ND + n) * 2 + j];
        }
    }
}

// ---------------- Kernel 2: fused priors + routing ----------------
// dynamic smem: 2-slot ring, 8 elements of 16B per thread per slot
#define RING_BYTES (2 * 8 * THREADS * 16)   // 147,456

__global__ __launch_bounds__(THREADS, 1)
void caps_routing_kernel(float* __restrict__ out)
{
    extern __shared__ ulonglong2 ring[];    // [2][8][THREADS]
    __shared__ float vred[NWARPS * 32];
    __shared__ float spred[NWARPS * 2];
    __shared__ float outv[32];

    const int tid  = threadIdx.x;
    const int lane = tid & 31;
    const int w    = tid >> 5;           // 0..17
    const int c    = blockIdx.x >> 6;
    const int b0   = (blockIdx.x & 63) * 2;

    const float4* __restrict__ xr0 = g_xT + (size_t)(b0 * 2) * ND;
    const float4* __restrict__ xr1 = g_xT + (size_t)((b0 + 1) * 2) * ND;
    const float4* __restrict__ wb4 = g_Wt + (size_t)c * 32 * ND + tid;

    const uint32_t sbase = (uint32_t)__cvta_generic_to_shared(ring) + tid * 16u;

    // prefetch group g (8 consecutive j's of rep g>>2) into ring slot
    auto issue = [&](int g, int slot) {
        const float4* src = wb4 + (size_t)((g & 3) * 8) * ND + (size_t)(g >> 2) * HALF;
        uint32_t dst = sbase + (uint32_t)(slot * 8 * THREADS * 16);
        #pragma unroll
        for (int e = 0; e < 8; e++)
            cp16(dst + e * (THREADS * 16), src + (size_t)e * ND);
        asm volatile("cp.async.commit_group;");
    };

    issue(0, 0);
    issue(1, 1);

    // rep0 x (plain LDG, hidden behind the first cp.async waits)
    float x0a[8], x0b[8], x1a[8], x1b[8];
    {
        float4 u0 = xr0[tid], u1 = xr0[ND + tid];
        float4 u2 = xr1[tid], u3 = xr1[ND + tid];
        x0a[0]=u0.x; x0a[1]=u0.y; x0a[2]=u0.z; x0a[3]=u0.w;
        x0a[4]=u1.x; x0a[5]=u1.y; x0a[6]=u1.z; x0a[7]=u1.w;
        x0b[0]=u2.x; x0b[1]=u2.y; x0b[2]=u2.z; x0b[3]=u2.w;
        x0b[4]=u3.x; x0b[5]=u3.y; x0b[6]=u3.z; x0b[7]=u3.w;
    }

    u64 pA0[8], pA1[8], pB0[8], pB1[8];
    #pragma unroll
    for (int k = 0; k < 8; k++) { pA0[k] = 0ull; pA1[k] = 0ull; }

    #pragma unroll
    for (int g = 0; g < 8; g++) {
        if (g == 7) asm volatile("cp.async.wait_group 0;");
        else        asm volatile("cp.async.wait_group 1;");

        if (g == 2) {   // rep1 x, two groups ahead of first use
            float4 u0 = xr0[HALF + tid], u1 = xr0[ND + HALF + tid];
            float4 u2 = xr1[HALF + tid], u3 = xr1[ND + HALF + tid];
            x1a[0]=u0.x; x1a[1]=u0.y; x1a[2]=u0.z; x1a[3]=u0.w;
            x1a[4]=u1.x; x1a[5]=u1.y; x1a[6]=u1.z; x1a[7]=u1.w;
            x1b[0]=u2.x; x1b[1]=u2.y; x1b[2]=u2.z; x1b[3]=u2.w;
            x1b[4]=u3.x; x1b[5]=u3.y; x1b[6]=u3.z; x1b[7]=u3.w;
        }
        if (g == 4) {
            #pragma unroll
            for (int k = 0; k < 8; k++) { pB0[k] = 0ull; pB1[k] = 0ull; }
        }

        {   // compute group g from slot g&1 (thread-private; no barrier)
            const int r = g >> 2;
            u64* A0 = r ? pB0 : pA0;
            u64* A1 = r ? pB1 : pA1;
            const float* fxa = r ? x1a : x0a;
            const float* fxb = r ? x1b : x0b;
            const ulonglong2* st = ring + (size_t)((g & 1) * 8) * THREADS + tid;
            #pragma unroll
            for (int hh = 0; hh < 2; hh++) {
                const int i = (g & 3) * 2 + hh;
                const u64 va2 = pk2(fxa[i], fxa[i]);
                const u64 vb2 = pk2(fxb[i], fxb[i]);
                #pragma unroll
                for (int qq = 0; qq < 4; qq++) {
                    ulonglong2 wv = st[(size_t)(hh * 4 + qq) * THREADS];
                    A0[2*qq+0] = ffma2(va2, wv.x, A0[2*qq+0]);
                    A0[2*qq+1] = ffma2(va2, wv.y, A0[2*qq+1]);
                    A1[2*qq+0] = ffma2(vb2, wv.x, A1[2*qq+0]);
                    A1[2*qq+1] = ffma2(vb2, wv.y, A1[2*qq+1]);
                }
            }
        }
        // refill the slot just consumed (its LDS reads executed ~29cyc after
        // issue; the async smem write lands >=L2-latency later)
        if (g < 6) issue(g + 2, g & 1);
    }

    float la0 = 0.f, la1 = 0.f, lb0 = 0.f, lb1 = 0.f;      // logits

    // ---------------- Phase B: iterations 0..2 ----------------
    #pragma unroll 1
    for (int it = 0; it < 3; it++) {
        u64 v02[8], v12[8];
        float sp0 = 0.f, sp1 = 0.f;

        if (it == 0) {
            // logits == 0: attention exactly uniform; S = ND.
            #pragma unroll
            for (int k = 0; k < 8; k++) {
                v02[k] = fadd2(pB0[k], pA0[k]);
                v12[k] = fadd2(pB1[k], pA1[k]);
            }
        } else {
            // fused: logit update -> exp -> weighted accumulation.
            // batch 0
            {
                u64 tA = 0ull, tB = 0ull;
                #pragma unroll
                for (int k = 0; k < 8; k++) {
                    const u64 ov2 = *reinterpret_cast<const u64*>(&outv[2*k]);
                    tA = ffma2(ov2, pA0[k], tA);
                    tB = ffma2(ov2, pB0[k], tB);
                }
                float aL, aH, bL, bH;
                upk2(aL, aH, tA); upk2(bL, bH, tB);
                la0 += aL + aH; lb0 += bL + bH;
                float eA = __expf(la0);
                float eB = __expf(lb0);
                sp0 = eA + eB;
                const u64 eA2 = pk2(eA, eA), eB2 = pk2(eB, eB);
                #pragma unroll
                for (int k = 0; k < 8; k++)
                    v02[k] = ffma2(eA2, pA0[k], fmul2(eB2, pB0[k]));
            }
            // batch 1
            {
                u64 tA = 0ull, tB = 0ull;
                #pragma unroll
                for (int k = 0; k < 8; k++) {
                    const u64 ov2 = *reinterpret_cast<const u64*>(&outv[16 + 2*k]);
                    tA = ffma2(ov2, pA1[k], tA);
                    tB = ffma2(ov2, pB1[k], tB);
                }
                float aL, aH, bL, bH;
                upk2(aL, aH, tA); upk2(bL, bH, tB);
                la1 += aL + aH; lb1 += bL + bH;
                float eA = __expf(la1);
                float eB = __expf(lb1);
                sp1 = eA + eB;
                const u64 eA2 = pk2(eA, eA), eB2 = pk2(eB, eB);
                #pragma unroll
                for (int k = 0; k < 8; k++)
                    v12[k] = ffma2(eA2, pA1[k], fmul2(eB2, pB1[k]));
            }
        }

        // unpack for the scalar shuffle butterfly
        float v0[16], v1[16];
        #pragma unroll
        for (int k = 0; k < 8; k++) {
            upk2(v0[2*k], v0[2*k+1], v02[k]);
            upk2(v1[2*k], v1[2*k+1], v12[k]);
        }

        // batch-merging component-splitting warp reduce (31 shfl):
        // bit-16 merges batches; bits 8/4/2/1 split components.
        float v[16];
        #pragma unroll
        for (int k = 0; k < 16; k++) {
            float s = (lane & 16) ? v0[k] : v1[k];
            float r = __shfl_xor_sync(0xffffffffu, s, 16);
            v[k] = ((lane & 16) ? v1[k] : v0[k]) + r;
        }
        #pragma unroll
        for (int k = 0; k < 8; k++) {
            float s = (lane & 8) ? v[k] : v[k + 8];
            float r = __shfl_xor_sync(0xffffffffu, s, 8);
            v[k] = ((lane & 8) ? v[k + 8] : v[k]) + r;
        }
        #pragma unroll
        for (int k = 0; k < 4; k++) {
            float s = (lane & 4) ? v[k] : v[k + 4];
            float r = __shfl_xor_sync(0xffffffffu, s, 4);
            v[k] = ((lane & 4) ? v[k + 4] : v[k]) + r;
        }
        #pragma unroll
        for (int k = 0; k < 2; k++) {
            float s = (lane & 2) ? v[k] : v[k + 2];
            float r = __shfl_xor_sync(0xffffffffu, s, 2);
            v[k] = ((lane & 2) ? v[k + 2] : v[k]) + r;
        }
        {
            float s = (lane & 1) ? v[0] : v[1];
            float r = __shfl_xor_sync(0xffffffffu, s, 1);
            v[0] = ((lane & 1) ? v[1] : v[0]) + r;
        }
        vred[w * 32 + lane] = v[0];

        if (it > 0) {   // sp: merge batches then butterfly
            float s = (lane & 16) ? sp0 : sp1;
            float r = __shfl_xor_sync(0xffffffffu, s, 16);
            float sp = ((lane & 16) ? sp1 : sp0) + r;
            #pragma unroll
            for (int d = 8; d; d >>= 1)
                sp += __shfl_xor_sync(0xffffffffu, sp, d);
            if ((lane & 15) == 0) spred[w * 2 + (lane >> 4)] = sp;
        }
        __syncthreads();

        // --- final 18-way reduce + squash (warp 0: lanes 0-15 bb0, 16-31 bb1) ---
        if (tid < 32) {
            const int fb = tid >> 4;
            float O = 0.f;
            #pragma unroll
            for (int j = 0; j < NWARPS; j++) O += vred[j * 32 + tid];
            float S;
            if (it == 0) {
                S = (float)ND;
            } else {
                S = 0.f;
                #pragma unroll
                for (int j = 0; j < NWARPS; j++) S += spred[j * 2 + fb];
            }
            float t = O / S;
            float sq = t * t;
            #pragma unroll
            for (int d = 8; d; d >>= 1)
                sq += __shfl_xor_sync(0xffffffffu, sq, d);
            float scale = sq / ((1.f + sq) * sqrtf(sq + 1e-8f));
            float val = t * scale;
            outv[tid] = val;
            if (it == 2)
                out[((size_t)(c * BD + b0 + fb)) * OUTD + (tid & 15)] = val;
        }
        __syncthreads();
    }
}

extern "C" void kernel_launch(void* const* d_in, const int* in_sizes, int n_in,
                              void* d_out, int out_size)
{
    const float* x = (const float*)d_in[0];
    const float* W = (const float*)d_in[1];
    // defensive: identify by size (x: 1,179,648 ; W: 1,474,560)
    if (n_in >= 2 && in_sizes[0] == CCAP * ND * 8 * OUTD) {
        x = (const float*)d_in[1];
        W = (const float*)d_in[0];
    }
    float* out = (float*)d_out;

    transpose_inputs_kernel<<<TP_WBLOCKS + TP_XBLOCKS, 256>>>(
        (const float4*)W, (const float4*)x);

    cudaFuncSetAttribute(caps_routing_kernel,
                         cudaFuncAttributeMaxDynamicSharedMemorySize, RING_BYTES);
    caps_routing_kernel<<<NBLOCKS, THREADS, RING_BYTES>>>(out);
}

// round 16
// speedup vs baseline: 1.4612x; 1.4612x over previous
#include <cuda_runtime.h>
#include <cstdint>

// CapsuleLayer dynamic routing. C=10,B=128,N=1152,IN=8,OUT=16, 3 iters.
//   1) tiled transpose W -> Wt4[c][j][n]; simple transpose x -> xT4[b][j][n]
//   2) fused priors + routing: one CTA per (c, b) -- TBATCH=1, 288 threads,
//      TWO CTAs resident per SM (launch_bounds(288,2)) so phase-A load
//      latency of one CTA overlaps phase-B compute of the other.
// Thread owns 4 route nodes (tid + r*288), priors fully register-resident
// packed f32x2 (4x8 u64 = 64 regs). Phase B: shift-free softmax (exact),
// fused logit-update/accumulation, 31-shuffle component-splitting warp
// butterfly; iteration 0 uses logits==0 -> uniform attention (S = N).

#define CCAP   10
#define BD     128
#define ND     1152
#define OUTD   16
#define THREADS 288
#define NWARPS  9
#define NBLOCKS (CCAP * BD)   // 1280

#define WT_ELEMS (CCAP * 32 * ND)   // 368,640 float4 (5.9 MB)
#define XT_ELEMS (BD * 2 * ND)      // 294,912 float4 (4.7 MB)

__device__ float4 g_Wt[WT_ELEMS];
__device__ float4 g_xT[XT_ELEMS];

typedef unsigned long long u64;

__device__ __forceinline__ u64 pk2(float a, float b) {
    u64 r; asm("mov.b64 %0, {%1, %2};" : "=l"(r) : "f"(a), "f"(b)); return r;
}
__device__ __forceinline__ void upk2(float& a, float& b, u64 v) {
    asm("mov.b64 {%0, %1}, %2;" : "=f"(a), "=f"(b) : "l"(v));
}
__device__ __forceinline__ u64 ffma2(u64 a, u64 b, u64 c) {
    u64 d; asm("fma.rn.f32x2 %0, %1, %2, %3;" : "=l"(d) : "l"(a), "l"(b), "l"(c)); return d;
}
__device__ __forceinline__ u64 fmul2(u64 a, u64 b) {
    u64 d; asm("mul.rn.f32x2 %0, %1, %2;" : "=l"(d) : "l"(a), "l"(b)); return d;
}
__device__ __forceinline__ u64 fadd2(u64 a, u64 b) {
    u64 d; asm("add.rn.f32x2 %0, %1, %2;" : "=l"(d) : "l"(a), "l"(b)); return d;
}

// ---------------- Kernel 1: transposes ----------------
#define TP_WBLOCKS (CCAP * 36)          // 360
#define TP_XBLOCKS (XT_ELEMS / 1024)    // 288

__global__ void transpose_inputs_kernel(const float4* __restrict__ W4,
                                        const float4* __restrict__ X4)
{
    if (blockIdx.x < TP_WBLOCKS) {
        __shared__ float4 tile[32][33];
        const int c  = blockIdx.x / 36;
        const int n0 = (blockIdx.x % 36) * 32;
        #pragma unroll
        for (int k = 0; k < 4; k++) {
            int flat = threadIdx.x + k * 256;
            int jr = flat & 31, nr = flat >> 5;
            tile[jr][nr] = W4[((size_t)(c * ND + n0 + nr)) * 32 + jr];
        }
        __syncthreads();
        #pragma unroll
        for (int k = 0; k < 4; k++) {
            int flat = threadIdx.x + k * 256;
            int nr = flat & 31, jr = flat >> 5;
            g_Wt[(size_t)(c * 32 + jr) * ND + n0 + nr] = tile[jr][nr];
        }
    } else {
        int base = (blockIdx.x - TP_WBLOCKS) * 1024 + threadIdx.x;
        #pragma unroll
        for (int k = 0; k < 4; k++) {
            int e = base + k * 256;
            int n = e % ND;
            int t = e / ND;
            int j = t & 1;
            int b = t >> 1;
            g_xT[e] = X4[((size_t)b * ND + n) * 2 + j];
        }
    }
}

// ---------------- Kernel 2: fused priors + routing ----------------
__global__ __launch_bounds__(THREADS, 2)
void caps_routing_kernel(float* __restrict__ out)
{
    __shared__ float vred[NWARPS * 16];
    __shared__ float spred[NWARPS];
    __shared__ __align__(8) float outv[16];

    const int tid  = threadIdx.x;
    const int lane = tid & 31;
    const int w    = tid >> 5;           // 0..8
    const int c    = blockIdx.x >> 7;    // /128
    const int b    = blockIdx.x & 127;

    const float4* __restrict__ xr = g_xT + (size_t)(b * 2) * ND;
    const ulonglong2* __restrict__ wb2 =
        (const ulonglong2*)(g_Wt + (size_t)c * 32 * ND);

    // -------- Phase A: priors for 4 nodes, packed f32x2 --------
    u64 p[4][8];

    #pragma unroll
    for (int r = 0; r < 4; r++) {
        const int n = tid + r * THREADS;
        float4 u0 = xr[n], u1 = xr[ND + n];
        float xs[8] = {u0.x, u0.y, u0.z, u0.w, u1.x, u1.y, u1.z, u1.w};

        #pragma unroll
        for (int k = 0; k < 8; k++) p[r][k] = 0ull;

        const ulonglong2* wp = wb2 + n;
        #pragma unroll
        for (int i = 0; i < 8; i++) {
            const u64 xv2 = pk2(xs[i], xs[i]);
            #pragma unroll
            for (int q = 0; q < 4; q++) {
                ulonglong2 wv = wp[(size_t)(i * 4 + q) * ND];
                p[r][2*q+0] = ffma2(xv2, wv.x, p[r][2*q+0]);
                p[r][2*q+1] = ffma2(xv2, wv.y, p[r][2*q+1]);
            }
        }
    }

    float lg[4] = {0.f, 0.f, 0.f, 0.f};     // logits (shift-free)

    // ---------------- Phase B: iterations 0..2 ----------------
    #pragma unroll 1
    for (int it = 0; it < 3; it++) {
        u64 v2[8];
        float sp = 0.f;

        if (it == 0) {
            // logits == 0: attention exactly uniform; S = ND.
            #pragma unroll
            for (int k = 0; k < 8; k++)
                v2[k] = fadd2(fadd2(p[0][k], p[1][k]), fadd2(p[2][k], p[3][k]));
        } else {
            // fused: logit update -> exp -> weighted accumulation.
            u64 ov2[8];
            #pragma unroll
            for (int k = 0; k < 8; k++)
                ov2[k] = *reinterpret_cast<const u64*>(&outv[2*k]);

            float e[4];
            #pragma unroll
            for (int r = 0; r < 4; r++) {
                u64 t = 0ull;
                #pragma unroll
                for (int k = 0; k < 8; k++) t = ffma2(ov2[k], p[r][k], t);
                float lo, hi; upk2(lo, hi, t);
                lg[r] += lo + hi;
                e[r] = __expf(lg[r]);
                sp += e[r];
            }
            const u64 e0 = pk2(e[0], e[0]), e1 = pk2(e[1], e[1]);
            const u64 e2 = pk2(e[2], e[2]), e3 = pk2(e[3], e[3]);
            #pragma unroll
            for (int k = 0; k < 8; k++) {
                u64 a = ffma2(e1, p[1][k], fmul2(e0, p[0][k]));
                u64 bq = ffma2(e3, p[3][k], fmul2(e2, p[2][k]));
                v2[k] = fadd2(a, bq);
            }
        }

        // unpack for the scalar shuffle butterfly
        float v[16];
        #pragma unroll
        for (int k = 0; k < 8; k++) upk2(v[2*k], v[2*k+1], v2[k]);

        // component-splitting warp reduce (31 shfl): bit-16 plain merge,
        // bits 8/4/2/1 split the 16 components; lane ends with comp lane&15.
        #pragma unroll
        for (int k = 0; k < 16; k++)
            v[k] += __shfl_xor_sync(0xffffffffu, v[k], 16);
        #pragma unroll
        for (int k = 0; k < 8; k++) {
            float s = (lane & 8) ? v[k] : v[k + 8];
            float r = __shfl_xor_sync(0xffffffffu, s, 8);
            v[k] = ((lane & 8) ? v[k + 8] : v[k]) + r;
        }
        #pragma unroll
        for (int k = 0; k < 4; k++) {
            float s = (lane & 4) ? v[k] : v[k + 4];
            float r = __shfl_xor_sync(0xffffffffu, s, 4);
            v[k] = ((lane & 4) ? v[k + 4] : v[k]) + r;
        }
        #pragma unroll
        for (int k = 0; k < 2; k++) {
            float s = (lane & 2) ? v[k] : v[k + 2];
            float r = __shfl_xor_sync(0xffffffffu, s, 2);
            v[k] = ((lane & 2) ? v[k + 2] : v[k]) + r;
        }
        {
            float s = (lane & 1) ? v[0] : v[1];
            float r = __shfl_xor_sync(0xffffffffu, s, 1);
            v[0] = ((lane & 1) ? v[1] : v[0]) + r;
        }
        if (lane < 16) vred[w * 16 + lane] = v[0];

        if (it > 0) {   // sp butterfly
            #pragma unroll
            for (int d = 16; d; d >>= 1)
                sp += __shfl_xor_sync(0xffffffffu, sp, d);
            if (lane == 0) spred[w] = sp;
        }
        __syncthreads();

        // --- final 9-way reduce + squash (warp 0; lanes 16-31 shadow) ---
        if (tid < 32) {
            const int comp = lane & 15;
            float O = 0.f;
            #pragma unroll
            for (int j = 0; j < NWARPS; j++) O += vred[j * 16 + comp];
            float S;
            if (it == 0) {
                S = (float)ND;
            } else {
                S = 0.f;
                #pragma unroll
                for (int j = 0; j < NWARPS; j++) S += spred[j];
            }
            float t = O / S;
            float sq = t * t;
            #pragma unroll
            for (int d = 8; d; d >>= 1)
                sq += __shfl_xor_sync(0xffffffffu, sq, d);
            float scale = sq / ((1.f + sq) * sqrtf(sq + 1e-8f));
            float val = t * scale;
            if (lane < 16) {
                outv[lane] = val;
                if (it == 2)
                    out[((size_t)(c * BD + b)) * OUTD + lane] = val;
            }
        }
        __syncthreads();
    }
}

extern "C" void kernel_launch(void* const* d_in, const int* in_sizes, int n_in,
                              void* d_out, int out_size)
{
    const float* x = (const float*)d_in[0];
    const float* W = (const float*)d_in[1];
    // defensive: identify by size (x: 1,179,648 ; W: 1,474,560)
    if (n_in >= 2 && in_sizes[0] == CCAP * ND * 8 * OUTD) {
        x = (const float*)d_in[1];
        W = (const float*)d_in[0];
    }
    float* out = (float*)d_out;

    transpose_inputs_kernel<<<TP_WBLOCKS + TP_XBLOCKS, 256>>>(
        (const float4*)W, (const float4*)x);

    caps_routing_kernel<<<NBLOCKS, THREADS>>>(out);
}